// round 8
// baseline (speedup 1.0000x reference)
#include <cuda_runtime.h>
#include <cuda_fp16.h>

// Problem constants
#define CUBE_L   512
#define EQU_H    1024
#define EQU_W    2048
#define N_EQU    4
#define N_CH     3
#define N_PIX    (EQU_H * EQU_W)        // 2,097,152
#define LL       (CUBE_L * CUBE_L)      // 262,144
#define N_PLANES (N_CH * 6)             // 18 packed planes (c,f)
#define IMG_STRIDE (6 * N_CH * LL)      // elements between equirect images in x

// Scratch: x repacked as x̃[(c*6+f)][y*L+x] = uint2 holding fp16 values for
// e = 0..3 (half2(e0,e1), half2(e2,e3)). 18 * 262144 * 8B = 37.75 MB.
__device__ uint2 g_xt[N_PLANES * LL];

static __device__ __forceinline__ unsigned int h2_as_u32(__half2 h) {
    return *reinterpret_cast<unsigned int*>(&h);
}
static __device__ __forceinline__ __half2 u32_as_h2(unsigned int u) {
    return *reinterpret_cast<__half2*>(&u);
}

// ---------------- Pass 1: repack (vectorized, 4 texels/thread) ---------------
__global__ __launch_bounds__(256)
void repack_kernel(const float* __restrict__ x)
{
    int T = blockIdx.x * blockDim.x + threadIdx.x;   // 0 .. 18*LL/4 - 1
    int plane = T >> 16;                 // / (LL/4)
    int i     = (T & 0xFFFF) << 2;       // 4 consecutive texels
    int c = plane / 6;
    int f = plane % 6;

    int base = f * (N_CH * LL) + c * LL + i;
    float4 a0 = *reinterpret_cast<const float4*>(x + base);
    float4 a1 = *reinterpret_cast<const float4*>(x + base + 1 * IMG_STRIDE);
    float4 a2 = *reinterpret_cast<const float4*>(x + base + 2 * IMG_STRIDE);
    float4 a3 = *reinterpret_cast<const float4*>(x + base + 3 * IMG_STRIDE);

    uint4 v01, v23;   // two texels each: (x,y)=texel j, (z,w)=texel j+1
    v01.x = h2_as_u32(__floats2half2_rn(a0.x, a1.x));
    v01.y = h2_as_u32(__floats2half2_rn(a2.x, a3.x));
    v01.z = h2_as_u32(__floats2half2_rn(a0.y, a1.y));
    v01.w = h2_as_u32(__floats2half2_rn(a2.y, a3.y));
    v23.x = h2_as_u32(__floats2half2_rn(a0.z, a1.z));
    v23.y = h2_as_u32(__floats2half2_rn(a2.z, a3.z));
    v23.z = h2_as_u32(__floats2half2_rn(a0.w, a1.w));
    v23.w = h2_as_u32(__floats2half2_rn(a2.w, a3.w));

    uint4* dst = reinterpret_cast<uint4*>(g_xt + plane * LL + i);
    dst[0] = v01;
    dst[1] = v23;
}

// ---------------- Pass 2: gather + bilinear, 2 pixels/thread -----------------
__global__ __launch_bounds__(256)
void cube2equirec_kernel(const float2* __restrict__ uv,
                         const int* __restrict__ face,
                         float* __restrict__ out)
{
    const int px = blockIdx.x * 64 + threadIdx.x * 2;  // 2 adjacent pixels
    const int py = blockIdx.y * 8  + threadIdx.y;
    const int p  = py * EQU_W + px;

    // uv for both pixels in one 16B load; face in one 8B load
    const float4 tt = *reinterpret_cast<const float4*>(uv + p);
    const int2  ff  = *reinterpret_cast<const int2*>(face + p);

    float uu[2] = {tt.x, tt.z};
    float vv[2] = {tt.y, tt.w};
    int   fcs[2] = {ff.x, ff.y};

    int   off[2][4];
    float w[2][4];
    #pragma unroll
    for (int k = 0; k < 2; k++) {
        int x0 = (int)floorf(uu[k]);
        int y0 = (int)floorf(vv[k]);
        x0 = min(max(x0, 0), CUBE_L - 1);
        y0 = min(max(y0, 0), CUBE_L - 1);
        int x1 = min(x0 + 1, CUBE_L - 1);
        int y1 = min(y0 + 1, CUBE_L - 1);
        float wx = uu[k] - (float)x0;
        float wy = vv[k] - (float)y0;
        w[k][0] = (1.0f - wx) * (1.0f - wy);
        w[k][1] = wx * (1.0f - wy);
        w[k][2] = (1.0f - wx) * wy;
        w[k][3] = wx * wy;
        off[k][0] = y0 * CUBE_L + x0;
        off[k][1] = y0 * CUBE_L + x1;
        off[k][2] = y1 * CUBE_L + x0;
        off[k][3] = y1 * CUBE_L + x1;
    }

    #pragma unroll
    for (int c = 0; c < N_CH; c++) {
        const uint2* b0 = g_xt + (c * 6 + fcs[0]) * LL;
        const uint2* b1 = g_xt + (c * 6 + fcs[1]) * LL;

        uint2 gA[4], gB[4];
        #pragma unroll
        for (int tap = 0; tap < 4; tap++) gA[tap] = __ldg(b0 + off[0][tap]);
        #pragma unroll
        for (int tap = 0; tap < 4; tap++) gB[tap] = __ldg(b1 + off[1][tap]);

        float rA[4] = {0.f, 0.f, 0.f, 0.f};  // e0..e3 pixel 0
        float rB[4] = {0.f, 0.f, 0.f, 0.f};  // e0..e3 pixel 1
        #pragma unroll
        for (int tap = 0; tap < 4; tap++) {
            float2 a01 = __half22float2(u32_as_h2(gA[tap].x));
            float2 a23 = __half22float2(u32_as_h2(gA[tap].y));
            rA[0] += w[0][tap] * a01.x;
            rA[1] += w[0][tap] * a01.y;
            rA[2] += w[0][tap] * a23.x;
            rA[3] += w[0][tap] * a23.y;
            float2 b01 = __half22float2(u32_as_h2(gB[tap].x));
            float2 b23 = __half22float2(u32_as_h2(gB[tap].y));
            rB[0] += w[1][tap] * b01.x;
            rB[1] += w[1][tap] * b01.y;
            rB[2] += w[1][tap] * b23.x;
            rB[3] += w[1][tap] * b23.y;
        }

        #pragma unroll
        for (int e = 0; e < N_EQU; e++) {
            float2 s = make_float2(rA[e], rB[e]);
            __stcs(reinterpret_cast<float2*>(out + (size_t)(e * N_CH + c) * N_PIX + p), s);
        }
    }
}

extern "C" void kernel_launch(void* const* d_in, const int* in_sizes, int n_in,
                              void* d_out, int out_size)
{
    const float*  x    = (const float*)d_in[0];
    const float2* uv   = (const float2*)d_in[1];
    const int*    face = (const int*)d_in[2];
    float*        out  = (float*)d_out;

    // Pass 1: repack, 4 texels per thread
    repack_kernel<<<(N_PLANES * LL / 4) / 256, 256>>>(x);

    // Pass 2: gather, 2 pixels per thread
    dim3 block(32, 8);
    dim3 grid(EQU_W / 64, EQU_H / 8);
    cube2equirec_kernel<<<grid, block>>>(uv, face, out);
}

// round 9
// speedup vs baseline: 1.0055x; 1.0055x over previous
#include <cuda_runtime.h>
#include <cuda_fp16.h>

// Problem constants
#define CUBE_L   512
#define EQU_H    1024
#define EQU_W    2048
#define N_EQU    4
#define N_CH     3
#define N_PIX    (EQU_H * EQU_W)        // 2,097,152
#define LL       (CUBE_L * CUBE_L)      // 262,144
#define N_PLANES (N_CH * 6)             // 18 packed planes (c,f)
#define IMG_STRIDE (6 * N_CH * LL)      // elements between equirect images in x

// Scratch: x repacked as x̃[(c*6+f)][y*L+x] = uint2 holding fp16 values for
// e = 0..3 (half2(e0,e1), half2(e2,e3)). 18 * 262144 * 8B = 37.75 MB.
__device__ uint2 g_xt[N_PLANES * LL];

static __device__ __forceinline__ unsigned int h2_as_u32(__half2 h) {
    return *reinterpret_cast<unsigned int*>(&h);
}
static __device__ __forceinline__ __half2 u32_as_h2(unsigned int u) {
    return *reinterpret_cast<__half2*>(&u);
}

// ---------------- Pass 1: repack (vectorized, 8 texels/thread) ---------------
__global__ __launch_bounds__(256)
void repack_kernel(const float* __restrict__ x)
{
    int T = blockIdx.x * blockDim.x + threadIdx.x;   // 0 .. 18*LL/8 - 1
    int plane = T >> 15;                 // / (LL/8)
    int i     = (T & 0x7FFF) << 3;       // 8 consecutive texels
    int c = plane / 6;
    int f = plane % 6;

    int base = f * (N_CH * LL) + c * LL + i;

    // Issue all 8 reads up front (2 x float4 per image, 4 images).
    float4 a[4][2];
    #pragma unroll
    for (int e = 0; e < 4; e++) {
        const float4* src = reinterpret_cast<const float4*>(x + base + e * IMG_STRIDE);
        a[e][0] = __ldg(src);
        a[e][1] = __ldg(src + 1);
    }

    uint4* dst = reinterpret_cast<uint4*>(g_xt + plane * LL + i);
    #pragma unroll
    for (int q = 0; q < 2; q++) {   // q: which float4 (texels 4q..4q+3)
        float4 a0 = a[0][q], a1 = a[1][q], a2 = a[2][q], a3 = a[3][q];
        uint4 v01, v23;
        v01.x = h2_as_u32(__floats2half2_rn(a0.x, a1.x));
        v01.y = h2_as_u32(__floats2half2_rn(a2.x, a3.x));
        v01.z = h2_as_u32(__floats2half2_rn(a0.y, a1.y));
        v01.w = h2_as_u32(__floats2half2_rn(a2.y, a3.y));
        v23.x = h2_as_u32(__floats2half2_rn(a0.z, a1.z));
        v23.y = h2_as_u32(__floats2half2_rn(a2.z, a3.z));
        v23.z = h2_as_u32(__floats2half2_rn(a0.w, a1.w));
        v23.w = h2_as_u32(__floats2half2_rn(a2.w, a3.w));
        dst[2 * q + 0] = v01;
        dst[2 * q + 1] = v23;
    }
}

// ---------------- Pass 2: gather + bilinear (R7 config: 1 px/thread) ---------
__global__ __launch_bounds__(256)
void cube2equirec_kernel(const float2* __restrict__ uv,
                         const int* __restrict__ face,
                         float* __restrict__ out)
{
    const int px = blockIdx.x * 32 + threadIdx.x;
    const int py = blockIdx.y * 8  + threadIdx.y;
    const int p  = py * EQU_W + px;

    const float2 t = uv[p];
    const float u = t.x, v = t.y;
    const int f = face[p];

    int x0 = (int)floorf(u);
    int y0 = (int)floorf(v);
    x0 = min(max(x0, 0), CUBE_L - 1);
    y0 = min(max(y0, 0), CUBE_L - 1);
    const int x1 = min(x0 + 1, CUBE_L - 1);
    const int y1 = min(y0 + 1, CUBE_L - 1);
    const float wx = u - (float)x0;
    const float wy = v - (float)y0;

    const float w00 = (1.0f - wx) * (1.0f - wy);
    const float w01 = wx * (1.0f - wy);
    const float w10 = (1.0f - wx) * wy;
    const float w11 = wx * wy;

    const int o00 = y0 * CUBE_L + x0;
    const int o01 = y0 * CUBE_L + x1;
    const int o10 = y1 * CUBE_L + x0;
    const int o11 = y1 * CUBE_L + x1;

    // Issue all 12 gathers up front (MLP).
    uint2 g[N_CH][4];
    #pragma unroll
    for (int c = 0; c < N_CH; c++) {
        const uint2* b = g_xt + (c * 6 + f) * LL;
        g[c][0] = __ldg(b + o00);
        g[c][1] = __ldg(b + o01);
        g[c][2] = __ldg(b + o10);
        g[c][3] = __ldg(b + o11);
    }

    const float w[4] = {w00, w01, w10, w11};

    #pragma unroll
    for (int c = 0; c < N_CH; c++) {
        float r01x = 0.f, r01y = 0.f, r23x = 0.f, r23y = 0.f;
        #pragma unroll
        for (int tap = 0; tap < 4; tap++) {
            float2 a01 = __half22float2(u32_as_h2(g[c][tap].x)); // e0,e1
            float2 a23 = __half22float2(u32_as_h2(g[c][tap].y)); // e2,e3
            r01x += w[tap] * a01.x;
            r01y += w[tap] * a01.y;
            r23x += w[tap] * a23.x;
            r23y += w[tap] * a23.y;
        }
        __stcs(out + (size_t)(0 * N_CH + c) * N_PIX + p, r01x);
        __stcs(out + (size_t)(1 * N_CH + c) * N_PIX + p, r01y);
        __stcs(out + (size_t)(2 * N_CH + c) * N_PIX + p, r23x);
        __stcs(out + (size_t)(3 * N_CH + c) * N_PIX + p, r23y);
    }
}

extern "C" void kernel_launch(void* const* d_in, const int* in_sizes, int n_in,
                              void* d_out, int out_size)
{
    const float*  x    = (const float*)d_in[0];
    const float2* uv   = (const float2*)d_in[1];
    const int*    face = (const int*)d_in[2];
    float*        out  = (float*)d_out;

    // Pass 1: repack, 8 texels per thread
    repack_kernel<<<(N_PLANES * LL / 8) / 256, 256>>>(x);

    // Pass 2: gather, 1 pixel per thread (R7 optimum)
    dim3 block(32, 8);
    dim3 grid(EQU_W / 32, EQU_H / 8);
    cube2equirec_kernel<<<grid, block>>>(uv, face, out);
}

// round 10
// speedup vs baseline: 1.0765x; 1.0705x over previous
#include <cuda_runtime.h>
#include <cuda_fp16.h>

// Problem constants
#define CUBE_L   512
#define EQU_H    1024
#define EQU_W    2048
#define N_EQU    4
#define N_CH     3
#define N_PIX    (EQU_H * EQU_W)        // 2,097,152
#define LL       (CUBE_L * CUBE_L)      // 262,144
#define N_PLANES (N_CH * 6)             // 18 packed planes (c,f)
#define IMG_STRIDE (6 * N_CH * LL)      // elements between equirect images in x

// Scratch: x repacked as x̃[(c*6+f)][y*L+x] = uint2 holding fp16 values for
// e = 0..3 (half2(e0,e1), half2(e2,e3)). 18 * 262144 * 8B = 37.75 MB.
__device__ uint2 g_xt[N_PLANES * LL];

static __device__ __forceinline__ unsigned int h2_as_u32(__half2 h) {
    return *reinterpret_cast<unsigned int*>(&h);
}
static __device__ __forceinline__ __half2 u32_as_h2(unsigned int u) {
    return *reinterpret_cast<__half2*>(&u);
}

// ---------------- Pass 1: repack (vectorized, 4 texels/thread — R8 config) ---
__global__ __launch_bounds__(256)
void repack_kernel(const float* __restrict__ x)
{
    int T = blockIdx.x * blockDim.x + threadIdx.x;   // 0 .. 18*LL/4 - 1
    int plane = T >> 16;                 // / (LL/4)
    int i     = (T & 0xFFFF) << 2;       // 4 consecutive texels
    int c = plane / 6;
    int f = plane % 6;

    int base = f * (N_CH * LL) + c * LL + i;
    float4 a0 = *reinterpret_cast<const float4*>(x + base);
    float4 a1 = *reinterpret_cast<const float4*>(x + base + 1 * IMG_STRIDE);
    float4 a2 = *reinterpret_cast<const float4*>(x + base + 2 * IMG_STRIDE);
    float4 a3 = *reinterpret_cast<const float4*>(x + base + 3 * IMG_STRIDE);

    uint4 v01, v23;   // two texels each: (x,y)=texel j, (z,w)=texel j+1
    v01.x = h2_as_u32(__floats2half2_rn(a0.x, a1.x));
    v01.y = h2_as_u32(__floats2half2_rn(a2.x, a3.x));
    v01.z = h2_as_u32(__floats2half2_rn(a0.y, a1.y));
    v01.w = h2_as_u32(__floats2half2_rn(a2.y, a3.y));
    v23.x = h2_as_u32(__floats2half2_rn(a0.z, a1.z));
    v23.y = h2_as_u32(__floats2half2_rn(a2.z, a3.z));
    v23.z = h2_as_u32(__floats2half2_rn(a0.w, a1.w));
    v23.w = h2_as_u32(__floats2half2_rn(a2.w, a3.w));

    uint4* dst = reinterpret_cast<uint4*>(g_xt + plane * LL + i);
    dst[0] = v01;
    dst[1] = v23;
}

// ---------------- Pass 2: gather + bilinear (R7 config: 1 px/thread) ---------
__global__ __launch_bounds__(256)
void cube2equirec_kernel(const float2* __restrict__ uv,
                         const int* __restrict__ face,
                         float* __restrict__ out)
{
    const int px = blockIdx.x * 32 + threadIdx.x;
    const int py = blockIdx.y * 8  + threadIdx.y;
    const int p  = py * EQU_W + px;

    const float2 t = uv[p];
    const float u = t.x, v = t.y;
    const int f = face[p];

    int x0 = (int)floorf(u);
    int y0 = (int)floorf(v);
    x0 = min(max(x0, 0), CUBE_L - 1);
    y0 = min(max(y0, 0), CUBE_L - 1);
    const int x1 = min(x0 + 1, CUBE_L - 1);
    const int y1 = min(y0 + 1, CUBE_L - 1);
    const float wx = u - (float)x0;
    const float wy = v - (float)y0;

    const float w00 = (1.0f - wx) * (1.0f - wy);
    const float w01 = wx * (1.0f - wy);
    const float w10 = (1.0f - wx) * wy;
    const float w11 = wx * wy;

    const int o00 = y0 * CUBE_L + x0;
    const int o01 = y0 * CUBE_L + x1;
    const int o10 = y1 * CUBE_L + x0;
    const int o11 = y1 * CUBE_L + x1;

    // Issue all 12 gathers up front (MLP).
    uint2 g[N_CH][4];
    #pragma unroll
    for (int c = 0; c < N_CH; c++) {
        const uint2* b = g_xt + (c * 6 + f) * LL;
        g[c][0] = __ldg(b + o00);
        g[c][1] = __ldg(b + o01);
        g[c][2] = __ldg(b + o10);
        g[c][3] = __ldg(b + o11);
    }

    const float w[4] = {w00, w01, w10, w11};

    #pragma unroll
    for (int c = 0; c < N_CH; c++) {
        float r01x = 0.f, r01y = 0.f, r23x = 0.f, r23y = 0.f;
        #pragma unroll
        for (int tap = 0; tap < 4; tap++) {
            float2 a01 = __half22float2(u32_as_h2(g[c][tap].x)); // e0,e1
            float2 a23 = __half22float2(u32_as_h2(g[c][tap].y)); // e2,e3
            r01x += w[tap] * a01.x;
            r01y += w[tap] * a01.y;
            r23x += w[tap] * a23.x;
            r23y += w[tap] * a23.y;
        }
        __stcs(out + (size_t)(0 * N_CH + c) * N_PIX + p, r01x);
        __stcs(out + (size_t)(1 * N_CH + c) * N_PIX + p, r01y);
        __stcs(out + (size_t)(2 * N_CH + c) * N_PIX + p, r23x);
        __stcs(out + (size_t)(3 * N_CH + c) * N_PIX + p, r23y);
    }
}

extern "C" void kernel_launch(void* const* d_in, const int* in_sizes, int n_in,
                              void* d_out, int out_size)
{
    const float*  x    = (const float*)d_in[0];
    const float2* uv   = (const float2*)d_in[1];
    const int*    face = (const int*)d_in[2];
    float*        out  = (float*)d_out;

    // Pass 1: repack, 4 texels per thread (fastest measured repack)
    repack_kernel<<<(N_PLANES * LL / 4) / 256, 256>>>(x);

    // Pass 2: gather, 1 pixel per thread (fastest measured gather)
    dim3 block(32, 8);
    dim3 grid(EQU_W / 32, EQU_H / 8);
    cube2equirec_kernel<<<grid, block>>>(uv, face, out);
}